// round 2
// baseline (speedup 1.0000x reference)
#include <cuda_runtime.h>

#define NN 64
#define PITCH 68
#define NB (NN * PITCH)   // 4352 floats per 64x64 buffer
#define PI_D 3.14159265358979323846

typedef unsigned long long ull;

// Tap tables (periodic circulant kernels), extended range [0,168):
//  Gdup[t] = {g(t), g(t)}        (duplicated pair, for left-multiplies)
//  Gpr[t]  = {g(t), g(t+1)}      (adjacent pair, for right-multiplies)
// g(t) = (1/64)(1 + 2*sum_{k=1..31} cos(pi*k*(2t+1)/64))   [periodic in t mod 64]
// h(t) = (1/128)(1 + 2*sum_{k=1..31} cos(pi*k*(2t-1)/64))
__device__ float2 d_Gdup[168], d_Hdup[168], d_Gpr[168], d_Hpr[168];

__global__ void init_mats_kernel() {
    int t = threadIdx.x;
    if (t >= 168) return;
    double sg0 = 1.0, sg1 = 1.0, sh0 = 1.0, sh1 = 1.0;
    for (int k = 1; k <= 31; k++) {
        double a = PI_D * (double)k / 64.0;
        sg0 += 2.0 * cos(a * (2.0 * (double)t + 1.0));
        sg1 += 2.0 * cos(a * (2.0 * (double)(t + 1) + 1.0));
        sh0 += 2.0 * cos(a * (2.0 * (double)t - 1.0));
        sh1 += 2.0 * cos(a * (2.0 * (double)(t + 1) - 1.0));
    }
    float g0 = (float)(sg0 / 64.0), g1 = (float)(sg1 / 64.0);
    float h0 = (float)(sh0 / 128.0), h1 = (float)(sh1 / 128.0);
    d_Gdup[t] = make_float2(g0, g0);
    d_Hdup[t] = make_float2(h0, h0);
    d_Gpr[t]  = make_float2(g0, g1);
    d_Hpr[t]  = make_float2(h0, h1);
}

__device__ __forceinline__ ull f2x2(float lo, float hi) {
    ull r;
    asm("mov.b64 %0, {%1, %2};" : "=l"(r) : "f"(lo), "f"(hi));
    return r;
}
__device__ __forceinline__ void ffma2(ull& d, ull a, ull b) {
    asm("fma.rn.f32x2 %0, %1, %2, %0;" : "+l"(d) : "l"(a), "l"(b));
}

// dst[r0+r][c0..c0+3] = sum_k g[(r0+r)-k] * src[k][c0..c0+3]
// 8 rows x 4 cols per thread; taps from duplicated-pair table Gd (index d+64).
__device__ __forceinline__ void mm_left(float* __restrict__ dst,
                                        const float* __restrict__ src,
                                        const float2* __restrict__ Gd,
                                        int r0, int c0) {
    ull acc[8][2];
    #pragma unroll
    for (int r = 0; r < 8; r++) { acc[r][0] = 0ull; acc[r][1] = 0ull; }
    #pragma unroll 2
    for (int kb = 0; kb < 64; kb += 8) {
        ull g[15];
        const ull* gp = (const ull*)&Gd[r0 - kb + 57];  // g[w] = dup(g(r0-kb-7+w))
        #pragma unroll
        for (int w = 0; w < 15; w++) g[w] = gp[w];
        #pragma unroll
        for (int q = 0; q < 8; q++) {
            ulonglong2 s = *(const ulonglong2*)&src[(kb + q) * PITCH + c0];
            #pragma unroll
            for (int r = 0; r < 8; r++) {
                ull a = g[r - q + 7];   // dup(g[(r0+r)-(kb+q)])
                ffma2(acc[r][0], a, s.x);
                ffma2(acc[r][1], a, s.y);
            }
        }
    }
    #pragma unroll
    for (int r = 0; r < 8; r++) {
        ulonglong2 o; o.x = acc[r][0]; o.y = acc[r][1];
        *(ulonglong2*)&dst[(r0 + r) * PITCH + c0] = o;
    }
}

// dst[i][m] = sum_k src[i][k] * c[m-k]   for i in r0..r0+3, m in c0..c0+7
// 4 rows x 8 cols per thread; taps from adjacent-pair table Cp (index d+64).
__device__ __forceinline__ void mm_right(float* __restrict__ dst,
                                         const float* __restrict__ src,
                                         const float2* __restrict__ Cp,
                                         int r0, int c0) {
    ull acc[4][4];
    #pragma unroll
    for (int i = 0; i < 4; i++)
        #pragma unroll
        for (int p = 0; p < 4; p++) acc[i][p] = 0ull;
    #pragma unroll 2
    for (int kb = 0; kb < 64; kb += 8) {
        ull h[14];
        const ull* hp = (const ull*)&Cp[c0 - kb + 57];  // h[w] = pair(c(c0-kb-7+w))
        #pragma unroll
        for (int w = 0; w < 14; w++) h[w] = hp[w];
        #pragma unroll
        for (int i = 0; i < 4; i++) {
            float4 va = *(const float4*)&src[(r0 + i) * PITCH + kb];
            float4 vb = *(const float4*)&src[(r0 + i) * PITCH + kb + 4];
            float sv[8] = {va.x, va.y, va.z, va.w, vb.x, vb.y, vb.z, vb.w};
            #pragma unroll
            for (int q = 0; q < 8; q++) {
                ull sd = f2x2(sv[q], sv[q]);
                #pragma unroll
                for (int p = 0; p < 4; p++)
                    ffma2(acc[i][p], sd, h[2 * p - q + 7]);  // pair(c[c0+2p-(kb+q)])
            }
        }
    }
    #pragma unroll
    for (int i = 0; i < 4; i++) {
        ulonglong2 o0; o0.x = acc[i][0]; o0.y = acc[i][1];
        ulonglong2 o1; o1.x = acc[i][2]; o1.y = acc[i][3];
        *(ulonglong2*)&dst[(r0 + i) * PITCH + c0]     = o0;
        *(ulonglong2*)&dst[(r0 + i) * PITCH + c0 + 4] = o1;
    }
}

__global__ void __launch_bounds__(128, 2)
uppolyact_kernel(const float* __restrict__ xg,
                 const float* __restrict__ coef,
                 float* __restrict__ outg) {
    extern __shared__ float sm[];
    float* SX = sm;            // x                  (kept for final affine)
    float* S1 = sm + NB;       // x G^T  -> p_eo^2
    float* S2 = sm + 2 * NB;   // G x    -> p_oe^2 -> tmp
    float* S3 = sm + 3 * NB;   // G x G^T -> p_oo^2 -> p_eo H^T
    float* S5 = sm + 4 * NB;   // p_ee^2
    float* S6 = sm + 5 * NB;   // p_oo H^T -> H tmp
    float2* Gds = (float2*)(sm + 6 * NB);
    float2* Hds = Gds + 168;
    float2* Gps = Hds + 168;
    float2* Hps = Gps + 168;
    float* rs  = (float*)(Hps + 168);  // 64: sum_i (-1)^i x[i][j]
    float* cs  = rs + 64;              // 64: sum_j (-1)^j x[i][j]
    float* rs1 = cs + 64;              // 64: col alt-sums of S1
    float* cs2 = rs1 + 64;             // 64: row alt-sums of S2
    float* tsp = cs2 + 64;             // 1

    const int tid = threadIdx.x;
    // map A (left-mult / elementwise / output): 8 rows x 4 cols
    const int r0a = (tid >> 4) << 3, c0a = (tid & 15) << 2;
    // map B (right-mult): 4 rows x 8 cols
    const int r0b = (tid >> 3) << 2, c0b = (tid & 7) << 3;

    const float* xin = xg + (size_t)blockIdx.x * 4096;
    float* outp = outg + (size_t)blockIdx.x * 4096;

    for (int i = tid; i < 168; i += 128) {
        Gds[i] = d_Gdup[i]; Hds[i] = d_Hdup[i];
        Gps[i] = d_Gpr[i];  Hps[i] = d_Hpr[i];
    }
    // Load image (contiguous 64x64) into padded smem
    #pragma unroll
    for (int i = tid; i < 1024; i += 128) {
        float4 v = ((const float4*)xin)[i];
        *(float4*)&SX[(i >> 4) * PITCH + ((i & 15) << 2)] = v;
    }
    __syncthreads();

    // S2 = G x ; S1 = x G^T  (both read only SX)
    mm_left (S2, SX, Gds, r0a, c0a);
    mm_right(S1, SX, Gps, r0b, c0b);
    __syncthreads();

    // Alternating-sign reductions for rank-1 even-phase corrections
    if (tid < 64) {
        int t = tid;
        float s = 0.f, s1 = 0.f;
        for (int i = 0; i < 64; i += 2) {
            s  += SX[i * PITCH + t] - SX[(i + 1) * PITCH + t];
            s1 += S1[i * PITCH + t] - S1[(i + 1) * PITCH + t];
        }
        rs[t] = s; rs1[t] = s1;
    } else {
        int t = tid - 64;
        float s = 0.f, s2 = 0.f;
        const float* rowx = &SX[t * PITCH];
        const float* row2 = &S2[t * PITCH];
        for (int j = 0; j < 64; j += 4) {
            float4 a = *(const float4*)&rowx[j];
            float4 b = *(const float4*)&row2[j];
            s  += (a.x - a.y) + (a.z - a.w);
            s2 += (b.x - b.y) + (b.z - b.w);
        }
        cs[t] = s; cs2[t] = s2;
    }
    __syncthreads();

    if (tid == 0) {
        float s = 0.f;
        for (int j = 0; j < 64; j += 2) s += rs[j] - rs[j + 1];
        tsp[0] = s;
    }
    // S3 = (G x) G^T
    mm_right(S3, S2, Gps, r0b, c0b);
    __syncthreads();

    // Apply even-phase rank-1 corrections and square all four polyphases (map A)
    {
        const float ts = tsp[0];
        const float inv64 = 1.0f / 64.0f;
        const float inv4096 = inv64 * inv64;
        #pragma unroll
        for (int r = 0; r < 8; r++) {
            int i = r0a + r;
            float sgni = (i & 1) ? -1.f : 1.f;
            float csv  = cs[i]  * inv64;
            float cs2v = cs2[i] * inv64;
            int base = i * PITCH + c0a;
            float4 rv  = *(const float4*)&rs[c0a];
            float4 rv1 = *(const float4*)&rs1[c0a];
            float4 xv = *(float4*)&SX[base];
            float4 v1 = *(float4*)&S1[base];
            float4 v2 = *(float4*)&S2[base];
            float4 v3 = *(float4*)&S3[base];
            float4 ee, eo, oe, oo;
            float tci = sgni * ts * inv4096;
            ee.x = xv.x + sgni * rv.x * inv64 + csv + tci;
            ee.y = xv.y + sgni * rv.y * inv64 - csv - tci;
            ee.z = xv.z + sgni * rv.z * inv64 + csv + tci;
            ee.w = xv.w + sgni * rv.w * inv64 - csv - tci;
            eo.x = v1.x + sgni * rv1.x * inv64;
            eo.y = v1.y + sgni * rv1.y * inv64;
            eo.z = v1.z + sgni * rv1.z * inv64;
            eo.w = v1.w + sgni * rv1.w * inv64;
            oe.x = v2.x + cs2v;  oe.y = v2.y - cs2v;
            oe.z = v2.z + cs2v;  oe.w = v2.w - cs2v;
            oo = v3;
            ee.x *= ee.x; ee.y *= ee.y; ee.z *= ee.z; ee.w *= ee.w;
            eo.x *= eo.x; eo.y *= eo.y; eo.z *= eo.z; eo.w *= eo.w;
            oe.x *= oe.x; oe.y *= oe.y; oe.z *= oe.z; oe.w *= oe.w;
            oo.x *= oo.x; oo.y *= oo.y; oo.z *= oo.z; oo.w *= oo.w;
            *(float4*)&S5[base] = ee;
            *(float4*)&S1[base] = eo;
            *(float4*)&S2[base] = oe;
            *(float4*)&S3[base] = oo;
        }
    }
    __syncthreads();

    // S6 = p_oo H^T
    mm_right(S6, S3, Hps, r0b, c0b);
    __syncthreads();

    // tmp: S2 = 0.5*p_oe + p_oo H^T   (map A)
    #pragma unroll
    for (int r = 0; r < 8; r++) {
        int base = (r0a + r) * PITCH + c0a;
        float4 a = *(float4*)&S2[base];
        float4 b = *(float4*)&S6[base];
        *(float4*)&S2[base] = make_float4(0.5f * a.x + b.x, 0.5f * a.y + b.y,
                                          0.5f * a.z + b.z, 0.5f * a.w + b.w);
    }
    __syncthreads();

    // S6 = H * tmp ;  S3 = p_eo H^T
    mm_left (S6, S2, Hds, r0a, c0a);
    mm_right(S3, S1, Hps, r0b, c0b);
    __syncthreads();

    // out = c0 + c1*x + c2*(0.25*p_ee + 0.5*(p_eo H^T) + H*tmp)   (map A)
    {
        const float k0 = coef[0], k1 = coef[1], k2 = coef[2];
        #pragma unroll
        for (int r = 0; r < 8; r++) {
            int i = r0a + r;
            int base = i * PITCH + c0a;
            float4 xv = *(float4*)&SX[base];
            float4 ee = *(float4*)&S5[base];
            float4 eo = *(float4*)&S3[base];
            float4 ob = *(float4*)&S6[base];
            float4 o;
            o.x = k0 + k1 * xv.x + k2 * (0.25f * ee.x + 0.5f * eo.x + ob.x);
            o.y = k0 + k1 * xv.y + k2 * (0.25f * ee.y + 0.5f * eo.y + ob.y);
            o.z = k0 + k1 * xv.z + k2 * (0.25f * ee.z + 0.5f * eo.z + ob.z);
            o.w = k0 + k1 * xv.w + k2 * (0.25f * ee.w + 0.5f * eo.w + ob.w);
            *(float4*)&outp[i * 64 + c0a] = o;
        }
    }
}

extern "C" void kernel_launch(void* const* d_in, const int* in_sizes, int n_in,
                              void* d_out, int out_size) {
    const float* x    = (const float*)d_in[0];
    const float* coef = (const float*)d_in[1];
    float* out = (float*)d_out;

    init_mats_kernel<<<1, 192>>>();

    // 6 image buffers + 4 tap tables (168 float2 each) + reduction scratch
    int smem_bytes = 6 * NB * (int)sizeof(float)
                   + 4 * 168 * (int)sizeof(float2)
                   + (4 * 64 + 4) * (int)sizeof(float);   // ~111 KB
    cudaFuncSetAttribute(uppolyact_kernel,
                         cudaFuncAttributeMaxDynamicSharedMemorySize, smem_bytes);

    int nimg = in_sizes[0] / 4096;   // 4096 images of 64x64
    uppolyact_kernel<<<nimg, 128, smem_bytes>>>(x, coef, out);
}

// round 3
// speedup vs baseline: 1.3426x; 1.3426x over previous
#include <cuda_runtime.h>

#define PITCH 68
#define NB (64 * PITCH)   // 4352 floats per 64x64 buffer

typedef unsigned long long ull;

__device__ __forceinline__ ull f2x2(float lo, float hi) {
    ull r; asm("mov.b64 %0, {%1, %2};" : "=l"(r) : "f"(lo), "f"(hi)); return r;
}
__device__ __forceinline__ float2 unpk(ull v) {
    float2 r; asm("mov.b64 {%0, %1}, %2;" : "=f"(r.x), "=f"(r.y) : "l"(v)); return r;
}
__device__ __forceinline__ void ffma2(ull& d, ull a, ull b) {
    asm("fma.rn.f32x2 %0, %1, %2, %0;" : "+l"(d) : "l"(a), "l"(b));
}

// Dirichlet kernel value with integer-exact angle reduction:
//   dval(m) = sin(31.5*pi*m/64) / sin(0.5*pi*m/64), periodic in m mod 256.
__device__ __forceinline__ float dval(int m) {
    int r1 = (63 * m) & 255; if (r1 >= 128) r1 -= 256;
    int r2 = m & 255;        if (r2 >= 128) r2 -= 256;
    const float sc = 3.14159265358979323846f / 128.0f;
    return sinf((float)r1 * sc) / sinf((float)r2 * sc);
}

// acc[r][p] covers dst rows r0..r0+3, col pair (c0+2p, c0+2p+1):
// dst[i][j] = sum_k g[i-k] * src[k][j]   (left circulant), taps dup-pairs Gd[i]={g(i),g(i)}
__device__ __forceinline__ void mm_left_core(ull acc[4][2], const float* __restrict__ src,
                                             const float2* __restrict__ Gd, int r0, int c0) {
    #pragma unroll
    for (int r = 0; r < 4; r++) { acc[r][0] = 0ull; acc[r][1] = 0ull; }
    #pragma unroll 1
    for (int kb = 0; kb < 64; kb += 8) {
        ull g[11];
        const ull* gp = (const ull*)&Gd[r0 - kb + 57];   // g[w] = dup(g(r0-kb-7+w))
        #pragma unroll
        for (int w = 0; w < 11; w++) g[w] = gp[w];
        #pragma unroll
        for (int q = 0; q < 8; q++) {
            ulonglong2 s = *(const ulonglong2*)&src[(kb + q) * PITCH + c0];
            #pragma unroll
            for (int r = 0; r < 4; r++) {
                ull a = g[r - q + 7];   // dup(g[(r0+r)-(kb+q)])
                ffma2(acc[r][0], a, s.x);
                ffma2(acc[r][1], a, s.y);
            }
        }
    }
}

// dst[i][m] = sum_k src[i][k] * c[m-k]  (right by circulant^T), taps adj-pairs Cp[i]={c(i),c(i+1)}
__device__ __forceinline__ void mm_right_core(ull acc[4][2], const float* __restrict__ src,
                                              const float2* __restrict__ Cp, int r0, int c0) {
    #pragma unroll
    for (int r = 0; r < 4; r++) { acc[r][0] = 0ull; acc[r][1] = 0ull; }
    #pragma unroll 1
    for (int kb = 0; kb < 64; kb += 8) {
        ull h[11];
        const ull* hp = (const ull*)&Cp[c0 - kb + 57];   // h[w] = pair(c(c0-kb-7+w))
        #pragma unroll
        for (int w = 0; w < 11; w++) h[w] = hp[w];
        #pragma unroll
        for (int i = 0; i < 4; i++) {
            float4 va = *(const float4*)&src[(r0 + i) * PITCH + kb];
            float4 vb = *(const float4*)&src[(r0 + i) * PITCH + kb + 4];
            float sv[8] = {va.x, va.y, va.z, va.w, vb.x, vb.y, vb.z, vb.w};
            #pragma unroll
            for (int q = 0; q < 8; q++) {
                ull sd = f2x2(sv[q], sv[q]);
                ffma2(acc[i][0], sd, h[7 - q]);       // pair(c[c0   - (kb+q)])
                ffma2(acc[i][1], sd, h[9 - q]);       // pair(c[c0+2 - (kb+q)])
            }
        }
    }
}

__device__ __forceinline__ void store_acc(float* __restrict__ dst, ull acc[4][2],
                                          int r0, int c0) {
    #pragma unroll
    for (int r = 0; r < 4; r++) {
        ulonglong2 o; o.x = acc[r][0]; o.y = acc[r][1];
        *(ulonglong2*)&dst[(r0 + r) * PITCH + c0] = o;
    }
}

__global__ void __launch_bounds__(256, 3)
uppolyact_kernel(const float* __restrict__ xg,
                 const float* __restrict__ coef,
                 float* __restrict__ outg) {
    extern __shared__ float sm[];
    float* B0 = sm;            // x (kept until the end)
    float* B1 = sm + NB;       // G x    -> p_oe^2 -> tmp
    float* B2 = sm + 2 * NB;   // x G^T  -> p_eo^2
    float* B3 = sm + 3 * NB;   // G x G^T -> p_oo^2 -> H tmp
    float2* Gds = (float2*)(sm + 4 * NB);
    float2* Gps = Gds + 168;
    float2* Hds = Gps + 168;
    float2* Hps = Hds + 168;
    float* rs  = (float*)(Hps + 168);  // 64: sum_i (-1)^i x[i][j]
    float* cs  = rs + 64;              // 64: sum_j (-1)^j x[i][j]
    float* rs1 = cs + 64;              // 64: col alt-sums of xG^T
    float* cs2 = rs1 + 64;             // 64: row alt-sums of Gx
    float* tsp = cs2 + 64;             // 1

    const int tid = threadIdx.x;
    const int r0 = (tid >> 4) << 2;    // 16 row-groups of 4
    const int c0 = (tid & 15) << 2;    // 16 col-groups of 4
    const float* xin = xg + (size_t)blockIdx.x * 4096;
    float* outp = outg + (size_t)blockIdx.x * 4096;

    // Build tap tables in-kernel (exact integer angle reduction, ~1 entry/thread)
    for (int i = tid; i < 168; i += 256) {
        float g0 = dval(2 * i + 1) * (1.0f / 64.0f);
        float g1 = dval(2 * i + 3) * (1.0f / 64.0f);
        float h0 = dval(2 * i - 1) * (1.0f / 128.0f);
        float h1 = dval(2 * i + 1) * (1.0f / 128.0f);
        Gds[i] = make_float2(g0, g0);
        Gps[i] = make_float2(g0, g1);
        Hds[i] = make_float2(h0, h0);
        Hps[i] = make_float2(h0, h1);
    }
    // Load image into padded smem
    #pragma unroll
    for (int i = tid; i < 1024; i += 256) {
        float4 v = ((const float4*)xin)[i];
        *(float4*)&B0[(i >> 4) * PITCH + ((i & 15) << 2)] = v;
    }
    __syncthreads();

    // B1 = G x ; B2 = x G^T
    {
        ull a1[4][2], a2[4][2];
        mm_left_core (a1, B0, Gds, r0, c0);
        mm_right_core(a2, B0, Gps, r0, c0);
        __syncthreads();          // B0 readers done before nothing changes; barrier orders writes
        store_acc(B1, a1, r0, c0);
        store_acc(B2, a2, r0, c0);
    }
    __syncthreads();

    // Alternating-sign reductions (rank-1 even-phase corrections)
    {
        int g = tid >> 6, t = tid & 63;
        float s = 0.f;
        if (g == 0) {
            for (int i = 0; i < 64; i += 2) s += B0[i * PITCH + t] - B0[(i + 1) * PITCH + t];
            rs[t] = s;
        } else if (g == 1) {
            const float* row = &B0[t * PITCH];
            for (int j = 0; j < 64; j += 4) {
                float4 a = *(const float4*)&row[j];
                s += (a.x - a.y) + (a.z - a.w);
            }
            cs[t] = s;
        } else if (g == 2) {
            for (int i = 0; i < 64; i += 2) s += B2[i * PITCH + t] - B2[(i + 1) * PITCH + t];
            rs1[t] = s;
        } else {
            const float* row = &B1[t * PITCH];
            for (int j = 0; j < 64; j += 4) {
                float4 a = *(const float4*)&row[j];
                s += (a.x - a.y) + (a.z - a.w);
            }
            cs2[t] = s;
        }
    }
    __syncthreads();

    if (tid == 0) {
        float s = 0.f;
        for (int j = 0; j < 64; j += 2) s += rs[j] - rs[j + 1];
        tsp[0] = s;
    }
    // B3 = (G x) G^T
    {
        ull a3[4][2];
        mm_right_core(a3, B1, Gps, r0, c0);
        store_acc(B3, a3, r0, c0);
    }
    __syncthreads();

    // Square odd phases in place (p_ee deferred to final epilogue)
    {
        const float inv64 = 1.0f / 64.0f;
        #pragma unroll
        for (int r = 0; r < 4; r++) {
            int i = r0 + r;
            float sgni = (i & 1) ? -1.f : 1.f;
            float cs2v = cs2[i] * inv64;
            int base = i * PITCH + c0;
            float4 rv1 = *(const float4*)&rs1[c0];
            float4 v1 = *(float4*)&B1[base];   // Gx   -> oe
            float4 v2 = *(float4*)&B2[base];   // xG^T -> eo
            float4 v3 = *(float4*)&B3[base];   // GxG^T = oo
            float4 eo, oe, oo;
            eo.x = v2.x + sgni * rv1.x * inv64;
            eo.y = v2.y + sgni * rv1.y * inv64;
            eo.z = v2.z + sgni * rv1.z * inv64;
            eo.w = v2.w + sgni * rv1.w * inv64;
            oe.x = v1.x + cs2v;  oe.y = v1.y - cs2v;
            oe.z = v1.z + cs2v;  oe.w = v1.w - cs2v;
            oo = v3;
            eo.x *= eo.x; eo.y *= eo.y; eo.z *= eo.z; eo.w *= eo.w;
            oe.x *= oe.x; oe.y *= oe.y; oe.z *= oe.z; oe.w *= oe.w;
            oo.x *= oo.x; oo.y *= oo.y; oo.z *= oo.z; oo.w *= oo.w;
            *(float4*)&B2[base] = eo;
            *(float4*)&B1[base] = oe;
            *(float4*)&B3[base] = oo;
        }
    }
    __syncthreads();

    // tmp: B1 = 0.5*B1 + B3*H^T   (fused epilogue, in-place on own tile)
    {
        ull acc[4][2];
        mm_right_core(acc, B3, Hps, r0, c0);
        #pragma unroll
        for (int r = 0; r < 4; r++) {
            int base = (r0 + r) * PITCH + c0;
            float4 d = *(float4*)&B1[base];
            float2 a0 = unpk(acc[r][0]), a1 = unpk(acc[r][1]);
            d.x = 0.5f * d.x + a0.x;  d.y = 0.5f * d.y + a0.y;
            d.z = 0.5f * d.z + a1.x;  d.w = 0.5f * d.w + a1.y;
            *(float4*)&B1[base] = d;
        }
    }
    __syncthreads();

    // B3 = H * tmp
    {
        ull acc[4][2];
        mm_left_core(acc, B1, Hds, r0, c0);
        store_acc(B3, acc, r0, c0);
    }
    __syncthreads();

    // Final: acc = p_eo^2 * H^T ; out = k0 + k1*x + k2*(0.25*ee^2 + 0.5*acc + Htmp)
    {
        ull acc[4][2];
        mm_right_core(acc, B2, Hps, r0, c0);
        const float k0 = __ldg(&coef[0]), k1 = __ldg(&coef[1]), k2 = __ldg(&coef[2]);
        const float ts = tsp[0];
        const float inv64 = 1.0f / 64.0f;
        const float inv4096 = inv64 * inv64;
        float4 rv = *(const float4*)&rs[c0];
        #pragma unroll
        for (int r = 0; r < 4; r++) {
            int i = r0 + r;
            float sgni = (i & 1) ? -1.f : 1.f;
            int base = i * PITCH + c0;
            float4 xv = *(float4*)&B0[base];
            float4 ht = *(float4*)&B3[base];
            float2 a0 = unpk(acc[r][0]), a1 = unpk(acc[r][1]);
            float csv = cs[i] * inv64;
            float tci = sgni * ts * inv4096;
            float vx = xv.x + sgni * rv.x * inv64 + csv + tci;
            float vy = xv.y + sgni * rv.y * inv64 - csv - tci;
            float vz = xv.z + sgni * rv.z * inv64 + csv + tci;
            float vw = xv.w + sgni * rv.w * inv64 - csv - tci;
            float4 o;
            o.x = k0 + k1 * xv.x + k2 * (0.25f * vx * vx + 0.5f * a0.x + ht.x);
            o.y = k0 + k1 * xv.y + k2 * (0.25f * vy * vy + 0.5f * a0.y + ht.y);
            o.z = k0 + k1 * xv.z + k2 * (0.25f * vz * vz + 0.5f * a1.x + ht.z);
            o.w = k0 + k1 * xv.w + k2 * (0.25f * vw * vw + 0.5f * a1.y + ht.w);
            *(float4*)&outp[i * 64 + c0] = o;
        }
    }
}

extern "C" void kernel_launch(void* const* d_in, const int* in_sizes, int n_in,
                              void* d_out, int out_size) {
    const float* x    = (const float*)d_in[0];
    const float* coef = (const float*)d_in[1];
    float* out = (float*)d_out;

    // 4 image buffers + 4 tap tables (168 float2 each) + reduction scratch
    int smem_bytes = 4 * NB * (int)sizeof(float)
                   + 4 * 168 * (int)sizeof(float2)
                   + (4 * 64 + 4) * (int)sizeof(float);   // 76036 B ≈ 74.3 KB
    cudaFuncSetAttribute(uppolyact_kernel,
                         cudaFuncAttributeMaxDynamicSharedMemorySize, smem_bytes);

    int nimg = in_sizes[0] / 4096;   // 4096 images of 64x64
    uppolyact_kernel<<<nimg, 256, smem_bytes>>>(x, coef, out);
}

// round 4
// speedup vs baseline: 1.5638x; 1.1648x over previous
#include <cuda_runtime.h>

#define PITCH 68
#define NB (64 * PITCH)   // 4352 floats per padded 64x64 buffer

typedef unsigned long long ull;

__device__ __forceinline__ ull f2x2(float lo, float hi) {
    ull r; asm("mov.b64 %0, {%1, %2};" : "=l"(r) : "f"(lo), "f"(hi)); return r;
}
__device__ __forceinline__ float2 unpk(ull v) {
    float2 r; asm("mov.b64 {%0, %1}, %2;" : "=f"(r.x), "=f"(r.y) : "l"(v)); return r;
}
__device__ __forceinline__ void ffma2(ull& d, ull a, ull b) {
    asm("fma.rn.f32x2 %0, %1, %2, %0;" : "+l"(d) : "l"(a), "l"(b));
}

// Dirichlet kernel value with integer-exact angle reduction:
//   dval(m) = sin(31.5*pi*m/64) / sin(0.5*pi*m/64), periodic in m mod 256 (m odd here).
__device__ __forceinline__ float dval(int m) {
    int r1 = (63 * m) & 255; if (r1 >= 128) r1 -= 256;
    int r2 = m & 255;        if (r2 >= 128) r2 -= 256;
    const float sc = 3.14159265358979323846f / 128.0f;
    return sinf((float)r1 * sc) / sinf((float)r2 * sc);
}

// Left circulant: dst[i][j] = sum_k g(i-k-SH) * src[k][j], tile 4 rows x 4 cols.
// Gd[j] = dup-pair g(j-64), j in [0,128). Tap loads are warp-broadcast (2 distinct).
template<int SH>
__device__ __forceinline__ void mm_left_core(ull acc[4][2], const float* __restrict__ src,
                                             const ull* __restrict__ Gd, int r0, int c0) {
    #pragma unroll
    for (int r = 0; r < 4; r++) { acc[r][0] = 0ull; acc[r][1] = 0ull; }
    #pragma unroll 1
    for (int kb = 0; kb < 64; kb += 8) {
        ull g[11];
        const ull* gp = &Gd[r0 - kb + 57 - SH];     // g[w] = dup(g(r0-kb+w-7-SH))
        #pragma unroll
        for (int w = 0; w < 11; w++) g[w] = gp[w];
        #pragma unroll
        for (int q = 0; q < 8; q++) {
            ulonglong2 s = *(const ulonglong2*)&src[(kb + q) * PITCH + c0];
            #pragma unroll
            for (int r = 0; r < 4; r++) {
                ull a = g[r - q + 7];               // dup(g((r0+r)-(kb+q)-SH))
                ffma2(acc[r][0], a, s.x);
                ffma2(acc[r][1], a, s.y);
            }
        }
    }
}

// Right circulant^T: dst[i][m] = sum_k src[i][k] * g(m-k-SH), tile 4 rows x 4 cols.
// TR[r*16+c] = {g(4c+r-64), g(4c+r-63)}; lane tap loads are 16 consecutive float2
// (128 B, conflict-free); src loads are warp-broadcast.
template<int SH>
__device__ __forceinline__ void mm_right_core(ull acc[4][2], const float* __restrict__ src,
                                              const ull* __restrict__ TR, int r0, int cg) {
    #pragma unroll
    for (int r = 0; r < 4; r++) { acc[r][0] = 0ull; acc[r][1] = 0ull; }
    #pragma unroll 1
    for (int kb = 0; kb < 64; kb += 8) {
        ull t[10];
        const ull* tp = TR + (57 - SH - kb) * 16 + cg;   // row u+64 = 57-SH-kb+w
        #pragma unroll
        for (int w = 0; w < 10; w++) t[w] = tp[w * 16];
        #pragma unroll
        for (int i = 0; i < 4; i++) {
            float4 va = *(const float4*)&src[(r0 + i) * PITCH + kb];
            float4 vb = *(const float4*)&src[(r0 + i) * PITCH + kb + 4];
            float sv[8] = {va.x, va.y, va.z, va.w, vb.x, vb.y, vb.z, vb.w};
            #pragma unroll
            for (int q = 0; q < 8; q++) {
                ull sd = f2x2(sv[q], sv[q]);
                ffma2(acc[i][0], sd, t[7 - q]);   // {g(c0  -(kb+q)-SH), g(c0+1-..)}
                ffma2(acc[i][1], sd, t[9 - q]);   // {g(c0+2-(kb+q)-SH), g(c0+3-..)}
            }
        }
    }
}

__device__ __forceinline__ void store_acc(float* __restrict__ dst, ull acc[4][2],
                                          int r0, int c0) {
    #pragma unroll
    for (int r = 0; r < 4; r++) {
        ulonglong2 o; o.x = acc[r][0]; o.y = acc[r][1];
        *(ulonglong2*)&dst[(r0 + r) * PITCH + c0] = o;
    }
}

__global__ void __launch_bounds__(256, 3)
uppolyact_kernel(const float* __restrict__ xg,
                 const float* __restrict__ coef,
                 float* __restrict__ outg) {
    extern __shared__ float sm[];
    float* B0 = sm;            // x -> (GxG^T = oo) -> oo^2 -> F = G'*tmp
    float* B1 = sm + NB;       // Gx -> oe^2 -> tmp = oe^2 + oo^2 G'^T
    float* B2 = sm + 2 * NB;   // xG^T -> eo^2
    ull* Gd  = (ull*)(sm + 3 * NB);          // 128 dup-pairs (pad to 132)
    ull* TR  = Gd + 132;                     // 68 rows x 16 = 1088 pairs
    float* Sg  = (float*)(TR + 1088);        // 140: raw g(t), t = i-66
    float* rs  = Sg + 140;                   // 64: alt row-sums of x (per col)
    float* cs  = rs + 64;                    // 64: alt col-sums of x (per row)
    float* rs1 = cs + 64;                    // 64: alt row-sums of xG^T
    float* cs2 = rs1 + 64;                   // 64: alt col-sums of Gx
    float* tsp = cs2 + 64;                   // 1

    const int tid = threadIdx.x;
    const int r0 = (tid >> 4) << 2;    // 16 row-groups of 4
    const int cg = tid & 15;           // col-group
    const int c0 = cg << 2;
    const float* xin = xg + (size_t)blockIdx.x * 4096;
    float* outp = outg + (size_t)blockIdx.x * 4096;

    const float k0 = __ldg(&coef[0]), k1 = __ldg(&coef[1]);
    const float k2q = 0.25f * __ldg(&coef[2]);

    // Phase 0: raw taps + image load
    for (int i = tid; i < 140; i += 256)
        Sg[i] = (i < 136) ? dval(2 * (i - 66) + 1) * (1.0f / 64.0f) : 0.f;
    #pragma unroll
    for (int i = tid; i < 1024; i += 256) {
        float4 v = ((const float4*)xin)[i];
        *(float4*)&B0[(i >> 4) * PITCH + ((i & 15) << 2)] = v;
    }
    __syncthreads();

    // Phase 1: build tables.  Gd[j] = dup g(j-64) = dup Sg[j+2].
    for (int i = tid; i < 128; i += 256) Gd[i] = f2x2(Sg[i + 2], Sg[i + 2]);
    // TR[r*16+c] = {g(4c+r-64), g(4c+r-63)} = {Sg[4c+r+2], Sg[4c+r+3]}
    for (int i = tid; i < 1088; i += 256) {
        int r = i >> 4, c = i & 15;
        TR[i] = f2x2(Sg[4 * c + r + 2], Sg[4 * c + r + 3]);
    }
    __syncthreads();

    // B1 = G x ; B2 = x G^T
    {
        ull a1[4][2], a2[4][2];
        mm_left_core<0> (a1, B0, Gd, r0, c0);
        mm_right_core<0>(a2, B0, TR, r0, cg);
        store_acc(B1, a1, r0, c0);
        store_acc(B2, a2, r0, c0);
    }
    __syncthreads();

    // Alternating-sign reductions for rank-1 even-phase corrections
    {
        int g = tid >> 6, t = tid & 63;
        float s = 0.f;
        if (g == 0) {
            for (int i = 0; i < 64; i += 2) s += B0[i * PITCH + t] - B0[(i + 1) * PITCH + t];
            rs[t] = s;
        } else if (g == 1) {
            const float* row = &B0[t * PITCH];
            for (int j = 0; j < 64; j += 4) {
                float4 a = *(const float4*)&row[j];
                s += (a.x - a.y) + (a.z - a.w);
            }
            cs[t] = s;
        } else if (g == 2) {
            for (int i = 0; i < 64; i += 2) s += B2[i * PITCH + t] - B2[(i + 1) * PITCH + t];
            rs1[t] = s;
        } else {
            const float* row = &B1[t * PITCH];
            for (int j = 0; j < 64; j += 4) {
                float4 a = *(const float4*)&row[j];
                s += (a.x - a.y) + (a.z - a.w);
            }
            cs2[t] = s;
        }
    }
    __syncthreads();

    if (tid == 0) {
        float s = 0.f;
        for (int j = 0; j < 64; j += 2) s += rs[j] - rs[j + 1];
        tsp[0] = s;
    }

    // oo = (Gx) G^T (kept in regs), then squaring pass writes all three phases:
    // B0 <- oo^2, B1 <- oe^2, B2 <- eo^2   (own-tile in-place, no sync needed vs mm3)
    {
        ull a3[4][2];
        mm_right_core<0>(a3, B1, TR, r0, cg);
        const float inv64 = 1.0f / 64.0f;
        float4 rv1 = *(const float4*)&rs1[c0];
        #pragma unroll
        for (int r = 0; r < 4; r++) {
            int i = r0 + r;
            float sgni = (i & 1) ? -1.f : 1.f;
            float cs2v = cs2[i] * inv64;
            int base = i * PITCH + c0;
            float4 v1 = *(float4*)&B1[base];   // Gx   -> oe
            float4 v2 = *(float4*)&B2[base];   // xG^T -> eo
            float2 o0 = unpk(a3[r][0]), o1 = unpk(a3[r][1]);
            float4 eo, oe, oo;
            eo.x = v2.x + sgni * rv1.x * inv64;
            eo.y = v2.y + sgni * rv1.y * inv64;
            eo.z = v2.z + sgni * rv1.z * inv64;
            eo.w = v2.w + sgni * rv1.w * inv64;
            oe.x = v1.x + cs2v;  oe.y = v1.y - cs2v;
            oe.z = v1.z + cs2v;  oe.w = v1.w - cs2v;
            oo.x = o0.x; oo.y = o0.y; oo.z = o1.x; oo.w = o1.y;
            eo.x *= eo.x; eo.y *= eo.y; eo.z *= eo.z; eo.w *= eo.w;
            oe.x *= oe.x; oe.y *= oe.y; oe.z *= oe.z; oe.w *= oe.w;
            oo.x *= oo.x; oo.y *= oo.y; oo.z *= oo.z; oo.w *= oo.w;
            *(float4*)&B2[base] = eo;
            *(float4*)&B1[base] = oe;
            *(float4*)&B0[base] = oo;
        }
    }
    __syncthreads();

    // tmp: B1 = oe^2 + oo^2 G'^T   (G' taps = g(t-1); scale folded into k2q)
    {
        ull acc[4][2];
        mm_right_core<1>(acc, B0, TR, r0, cg);
        #pragma unroll
        for (int r = 0; r < 4; r++) {
            int base = (r0 + r) * PITCH + c0;
            float4 d = *(float4*)&B1[base];
            float2 a0 = unpk(acc[r][0]), a1 = unpk(acc[r][1]);
            d.x += a0.x;  d.y += a0.y;  d.z += a1.x;  d.w += a1.y;
            *(float4*)&B1[base] = d;
        }
    }
    __syncthreads();

    // B0 = F = G' * tmp
    {
        ull acc[4][2];
        mm_left_core<1>(acc, B1, Gd, r0, c0);
        store_acc(B0, acc, r0, c0);
    }
    __syncthreads();

    // Final: E = eo^2 G'^T (regs); re-read x from gmem; reconstruct ee;
    // out = k0 + k1*x + (k2/4)*(ee^2 + E + F)
    {
        float4 xv[4];
        #pragma unroll
        for (int r = 0; r < 4; r++)
            xv[r] = *(const float4*)&xin[(r0 + r) * 64 + c0];
        ull acc[4][2];
        mm_right_core<1>(acc, B2, TR, r0, cg);
        const float ts = tsp[0];
        const float inv64 = 1.0f / 64.0f;
        const float inv4096 = inv64 * inv64;
        float4 rv = *(const float4*)&rs[c0];
        #pragma unroll
        for (int r = 0; r < 4; r++) {
            int i = r0 + r;
            float sgni = (i & 1) ? -1.f : 1.f;
            float4 ht = *(float4*)&B0[i * PITCH + c0];
            float2 a0 = unpk(acc[r][0]), a1 = unpk(acc[r][1]);
            float csv = cs[i] * inv64;
            float tci = sgni * ts * inv4096;
            float vx = xv[r].x + sgni * rv.x * inv64 + csv + tci;
            float vy = xv[r].y + sgni * rv.y * inv64 - csv - tci;
            float vz = xv[r].z + sgni * rv.z * inv64 + csv + tci;
            float vw = xv[r].w + sgni * rv.w * inv64 - csv - tci;
            float4 o;
            o.x = k0 + k1 * xv[r].x + k2q * (vx * vx + a0.x + ht.x);
            o.y = k0 + k1 * xv[r].y + k2q * (vy * vy + a0.y + ht.y);
            o.z = k0 + k1 * xv[r].z + k2q * (vz * vz + a1.x + ht.z);
            o.w = k0 + k1 * xv[r].w + k2q * (vw * vw + a1.y + ht.w);
            *(float4*)&outp[i * 64 + c0] = o;
        }
    }
}

extern "C" void kernel_launch(void* const* d_in, const int* in_sizes, int n_in,
                              void* d_out, int out_size) {
    const float* x    = (const float*)d_in[0];
    const float* coef = (const float*)d_in[1];
    float* out = (float*)d_out;

    // 3 image buffers + dup table (132) + TR table (1088) + scratch
    int smem_bytes = 3 * NB * (int)sizeof(float)
                   + (132 + 1088) * (int)sizeof(ull)
                   + (140 + 4 * 64 + 4) * (int)sizeof(float);   // ~63.6 KB
    cudaFuncSetAttribute(uppolyact_kernel,
                         cudaFuncAttributeMaxDynamicSharedMemorySize, smem_bytes);

    int nimg = in_sizes[0] / 4096;   // 4096 images of 64x64
    uppolyact_kernel<<<nimg, 256, smem_bytes>>>(x, coef, out);
}

// round 5
// speedup vs baseline: 1.6003x; 1.0233x over previous
#include <cuda_runtime.h>

#define PITCH 68
#define NB (64 * PITCH)   // 4352 floats per padded 64x64 buffer

typedef unsigned long long ull;

__device__ __forceinline__ ull f2x2(float lo, float hi) {
    ull r; asm("mov.b64 %0, {%1, %2};" : "=l"(r) : "f"(lo), "f"(hi)); return r;
}
__device__ __forceinline__ float2 unpk(ull v) {
    float2 r; asm("mov.b64 {%0, %1}, %2;" : "=f"(r.x), "=f"(r.y) : "l"(v)); return r;
}
__device__ __forceinline__ void ffma2(ull& d, ull a, ull b) {
    asm("fma.rn.f32x2 %0, %1, %2, %0;" : "+l"(d) : "l"(a), "l"(b));
}

// Dirichlet kernel value with integer-exact angle reduction:
//   dval(m) = sin(31.5*pi*m/64) / sin(0.5*pi*m/64), periodic in m mod 256 (m odd).
__device__ __forceinline__ float dval(int m) {
    int r1 = (63 * m) & 255; if (r1 >= 128) r1 -= 256;
    int r2 = m & 255;        if (r2 >= 128) r2 -= 256;
    const float sc = 3.14159265358979323846f / 128.0f;
    return sinf((float)r1 * sc) / sinf((float)r2 * sc);
}

// Left circulant: dst[i][j] = sum_k g(i-k-SH) * src[k][j], tile 4 rows x 4 cols.
// QT[j] = { dup g(j-66), dup g(j-65) } (one 16B entry = two dup-pairs) ->
// 6 broadcast LDS.128 per 8-k chunk instead of 11 LDS.64.
template<int SH>
__device__ __forceinline__ void mm_left_core(ull acc[4][2], const float* __restrict__ src,
                                             const ulonglong2* __restrict__ QT,
                                             int r0, int c0) {
    #pragma unroll
    for (int r = 0; r < 4; r++) { acc[r][0] = 0ull; acc[r][1] = 0ull; }
    #pragma unroll 1
    for (int kb = 0; kb < 64; kb += 8) {
        ulonglong2 qv[6];
        const ulonglong2* qp = &QT[r0 - kb + 59 - SH];  // entry e covers w=2e,2e+1
        #pragma unroll
        for (int e = 0; e < 6; e++) qv[e] = qp[2 * e];
        #pragma unroll
        for (int q = 0; q < 8; q++) {
            ulonglong2 s = *(const ulonglong2*)&src[(kb + q) * PITCH + c0];
            #pragma unroll
            for (int r = 0; r < 4; r++) {
                const int w = r - q + 7;             // 0..10, compile-time
                ull a = (w & 1) ? qv[w >> 1].y : qv[w >> 1].x;  // dup g((r0+r)-(kb+q)-SH)
                ffma2(acc[r][0], a, s.x);
                ffma2(acc[r][1], a, s.y);
            }
        }
    }
}

// Right circulant^T: dst[i][m] = sum_k src[i][k] * g(m-k-SH), tile 4 rows x 4 cols.
// TR[r*16+c] = {g(4c+r-64), g(4c+r-63)}; lane taps are 16 consecutive float2
// (conflict-free); src loads are warp-broadcast.
template<int SH>
__device__ __forceinline__ void mm_right_core(ull acc[4][2], const float* __restrict__ src,
                                              const ull* __restrict__ TR, int r0, int cg) {
    #pragma unroll
    for (int r = 0; r < 4; r++) { acc[r][0] = 0ull; acc[r][1] = 0ull; }
    #pragma unroll 1
    for (int kb = 0; kb < 64; kb += 8) {
        ull t[10];
        const ull* tp = TR + (57 - SH - kb) * 16 + cg;
        #pragma unroll
        for (int w = 0; w < 10; w++) t[w] = tp[w * 16];
        #pragma unroll
        for (int i = 0; i < 4; i++) {
            float4 va = *(const float4*)&src[(r0 + i) * PITCH + kb];
            float4 vb = *(const float4*)&src[(r0 + i) * PITCH + kb + 4];
            float sv[8] = {va.x, va.y, va.z, va.w, vb.x, vb.y, vb.z, vb.w};
            #pragma unroll
            for (int q = 0; q < 8; q++) {
                ull sd = f2x2(sv[q], sv[q]);
                ffma2(acc[i][0], sd, t[7 - q]);   // {g(c0  -(kb+q)-SH), g(c0+1-..)}
                ffma2(acc[i][1], sd, t[9 - q]);   // {g(c0+2-(kb+q)-SH), g(c0+3-..)}
            }
        }
    }
}

__device__ __forceinline__ void store_acc(float* __restrict__ dst, ull acc[4][2],
                                          int r0, int c0) {
    #pragma unroll
    for (int r = 0; r < 4; r++) {
        ulonglong2 o; o.x = acc[r][0]; o.y = acc[r][1];
        *(ulonglong2*)&dst[(r0 + r) * PITCH + c0] = o;
    }
}

__global__ void __launch_bounds__(256, 3)
uppolyact_kernel(const float* __restrict__ xg,
                 const float* __restrict__ coef,
                 float* __restrict__ outg) {
    extern __shared__ float sm[];
    float* B0 = sm;            // x -> oo^2 -> F = G'*tmp
    float* B1 = sm + NB;       // Gx -> oe^2 -> tmp = oe^2 + oo^2 G'^T
    float* B2 = sm + 2 * NB;   // xG^T -> eo^2
    ulonglong2* QT = (ulonglong2*)(sm + 3 * NB);   // 132 quad-tap entries
    ull* TR  = (ull*)(QT + 132);             // 68 rows x 16 pairs
    float* Sg  = (float*)(TR + 1088);        // 141 raw taps g(i-66)
    float* Pr  = Sg + 144;                   // 16 x 68 partials (row-dir)
    float* Pc  = Pr + 1088;                  // 16 x 68 partials (col-dir)
    float* rs  = Pc + 1088;                  // 64
    float* cs  = rs + 64;                    // 64
    float* rs1 = cs + 64;                    // 64
    float* cs2 = rs1 + 64;                   // 64
    float* tsp = cs2 + 64;                   // 1

    const int tid = threadIdx.x;
    const int rg = tid >> 4, cg = tid & 15;
    const int r0 = rg << 2, c0 = cg << 2;
    const float* xin = xg + (size_t)blockIdx.x * 4096;
    float* outp = outg + (size_t)blockIdx.x * 4096;

    const float k0 = __ldg(&coef[0]), k1 = __ldg(&coef[1]);
    const float k2q = 0.25f * __ldg(&coef[2]);

    // ---- P0: raw taps; own-tile gmem load; B0 write; x rank-1 partials ----
    for (int i = tid; i < 141; i += 256)
        Sg[i] = (i < 137) ? dval(2 * (i - 66) + 1) * (1.0f / 64.0f) : 0.f;
    {
        float4 xv[4];
        #pragma unroll
        for (int r = 0; r < 4; r++) {
            xv[r] = *(const float4*)&xin[(r0 + r) * 64 + c0];
            *(float4*)&B0[(r0 + r) * PITCH + c0] = xv[r];
        }
        // Pr[rg][j] partial: sum_r (-1)^r x[r][j]   (r0 even so global sign +)
        float4 pr;
        pr.x = xv[0].x - xv[1].x + xv[2].x - xv[3].x;
        pr.y = xv[0].y - xv[1].y + xv[2].y - xv[3].y;
        pr.z = xv[0].z - xv[1].z + xv[2].z - xv[3].z;
        pr.w = xv[0].w - xv[1].w + xv[2].w - xv[3].w;
        *(float4*)&Pr[rg * 68 + c0] = pr;
        // Pc[cg][i] partial: sum_c (-1)^c x[i][c]
        float4 pc;
        pc.x = xv[0].x - xv[0].y + xv[0].z - xv[0].w;
        pc.y = xv[1].x - xv[1].y + xv[1].z - xv[1].w;
        pc.z = xv[2].x - xv[2].y + xv[2].z - xv[2].w;
        pc.w = xv[3].x - xv[3].y + xv[3].z - xv[3].w;
        *(float4*)&Pc[cg * 68 + r0] = pc;
    }
    __syncthreads();

    // ---- P0.5: reduce rs/cs (tid<64) ; build tables (tid>=64) ----
    if (tid < 64) {
        float s = 0.f, t = 0.f;
        #pragma unroll
        for (int g = 0; g < 16; g++) { s += Pr[g * 68 + tid]; t += Pc[g * 68 + tid]; }
        rs[tid] = s; cs[tid] = t;
    } else {
        int idx = tid - 64;   // 192 workers
        for (int i = idx; i < 132; i += 192)
            QT[i] = make_ulonglong2(f2x2(Sg[i], Sg[i]), f2x2(Sg[i + 1], Sg[i + 1]));
        for (int i = idx; i < 1088; i += 192) {
            int r = i >> 4, c = i & 15;
            TR[i] = f2x2(Sg[4 * c + r + 2], Sg[4 * c + r + 3]);
        }
    }
    __syncthreads();

    // ---- P1: B1 = G x ; B2 = x G^T ; rank-1 partials from accumulators ----
    {
        ull a1[4][2], a2[4][2];
        mm_left_core<0> (a1, B0, QT, r0, c0);
        mm_right_core<0>(a2, B0, TR, r0, cg);
        // rs1 partials: alt row-sums of xG^T (a2)
        float2 p0, p1;
        {
            float2 u0 = unpk(a2[0][0]), u1 = unpk(a2[1][0]),
                   u2 = unpk(a2[2][0]), u3 = unpk(a2[3][0]);
            p0.x = u0.x - u1.x + u2.x - u3.x;
            p0.y = u0.y - u1.y + u2.y - u3.y;
            u0 = unpk(a2[0][1]); u1 = unpk(a2[1][1]);
            u2 = unpk(a2[2][1]); u3 = unpk(a2[3][1]);
            p1.x = u0.x - u1.x + u2.x - u3.x;
            p1.y = u0.y - u1.y + u2.y - u3.y;
        }
        *(float4*)&Pr[rg * 68 + c0] = make_float4(p0.x, p0.y, p1.x, p1.y);
        // cs2 partials: alt col-sums of Gx (a1)
        float4 pc;
        {
            float2 v0 = unpk(a1[0][0]), w0 = unpk(a1[0][1]);
            float2 v1 = unpk(a1[1][0]), w1 = unpk(a1[1][1]);
            float2 v2 = unpk(a1[2][0]), w2 = unpk(a1[2][1]);
            float2 v3 = unpk(a1[3][0]), w3 = unpk(a1[3][1]);
            pc.x = v0.x - v0.y + w0.x - w0.y;
            pc.y = v1.x - v1.y + w1.x - w1.y;
            pc.z = v2.x - v2.y + w2.x - w2.y;
            pc.w = v3.x - v3.y + w3.x - w3.y;
        }
        *(float4*)&Pc[cg * 68 + r0] = pc;
        store_acc(B1, a1, r0, c0);
        store_acc(B2, a2, r0, c0);
    }
    __syncthreads();

    // ---- P1.5: reduce rs1/cs2 ; warp-reduce ts from rs ----
    if (tid < 64) {
        float s = 0.f, t = 0.f;
        #pragma unroll
        for (int g = 0; g < 16; g++) { s += Pr[g * 68 + tid]; t += Pc[g * 68 + tid]; }
        rs1[tid] = s; cs2[tid] = t;
    } else if (tid < 96) {
        int l = tid - 64;
        float v = rs[2 * l] - rs[2 * l + 1];
        #pragma unroll
        for (int o = 16; o > 0; o >>= 1)
            v += __shfl_xor_sync(0xffffffffu, v, o);
        if (l == 0) tsp[0] = v;
    }
    __syncthreads();

    // ---- P2: oo = (Gx) G^T in regs; square phases: B0<-oo^2 B1<-oe^2 B2<-eo^2 ----
    {
        ull a3[4][2];
        mm_right_core<0>(a3, B1, TR, r0, cg);
        const float inv64 = 1.0f / 64.0f;
        float4 rv1 = *(const float4*)&rs1[c0];
        #pragma unroll
        for (int r = 0; r < 4; r++) {
            int i = r0 + r;
            float sgni = (i & 1) ? -1.f : 1.f;
            float cs2v = cs2[i] * inv64;
            int base = i * PITCH + c0;
            float4 v1 = *(float4*)&B1[base];   // Gx   -> oe
            float4 v2 = *(float4*)&B2[base];   // xG^T -> eo
            float2 o0 = unpk(a3[r][0]), o1 = unpk(a3[r][1]);
            float4 eo, oe, oo;
            eo.x = v2.x + sgni * rv1.x * inv64;
            eo.y = v2.y + sgni * rv1.y * inv64;
            eo.z = v2.z + sgni * rv1.z * inv64;
            eo.w = v2.w + sgni * rv1.w * inv64;
            oe.x = v1.x + cs2v;  oe.y = v1.y - cs2v;
            oe.z = v1.z + cs2v;  oe.w = v1.w - cs2v;
            oo.x = o0.x; oo.y = o0.y; oo.z = o1.x; oo.w = o1.y;
            eo.x *= eo.x; eo.y *= eo.y; eo.z *= eo.z; eo.w *= eo.w;
            oe.x *= oe.x; oe.y *= oe.y; oe.z *= oe.z; oe.w *= oe.w;
            oo.x *= oo.x; oo.y *= oo.y; oo.z *= oo.z; oo.w *= oo.w;
            *(float4*)&B2[base] = eo;
            *(float4*)&B1[base] = oe;
            *(float4*)&B0[base] = oo;
        }
    }
    __syncthreads();

    // ---- P3: tmp: B1 = oe^2 + oo^2 G'^T   (G' = g shifted by 1) ----
    {
        ull acc[4][2];
        mm_right_core<1>(acc, B0, TR, r0, cg);
        #pragma unroll
        for (int r = 0; r < 4; r++) {
            int base = (r0 + r) * PITCH + c0;
            float4 d = *(float4*)&B1[base];
            float2 a0 = unpk(acc[r][0]), a1 = unpk(acc[r][1]);
            d.x += a0.x;  d.y += a0.y;  d.z += a1.x;  d.w += a1.y;
            *(float4*)&B1[base] = d;
        }
    }
    __syncthreads();

    // ---- P4: B0 = F = G' * tmp ----
    {
        ull acc[4][2];
        mm_left_core<1>(acc, B1, QT, r0, c0);
        store_acc(B0, acc, r0, c0);
    }
    __syncthreads();

    // ---- P5: E = eo^2 G'^T (regs); reconstruct ee; final combine + store ----
    {
        float4 xv[4];
        #pragma unroll
        for (int r = 0; r < 4; r++)
            xv[r] = *(const float4*)&xin[(r0 + r) * 64 + c0];
        ull acc[4][2];
        mm_right_core<1>(acc, B2, TR, r0, cg);
        const float ts = tsp[0];
        const float inv64 = 1.0f / 64.0f;
        const float inv4096 = inv64 * inv64;
        float4 rv = *(const float4*)&rs[c0];
        #pragma unroll
        for (int r = 0; r < 4; r++) {
            int i = r0 + r;
            float sgni = (i & 1) ? -1.f : 1.f;
            float4 ht = *(float4*)&B0[i * PITCH + c0];
            float2 a0 = unpk(acc[r][0]), a1 = unpk(acc[r][1]);
            float csv = cs[i] * inv64;
            float tci = sgni * ts * inv4096;
            float vx = xv[r].x + sgni * rv.x * inv64 + csv + tci;
            float vy = xv[r].y + sgni * rv.y * inv64 - csv - tci;
            float vz = xv[r].z + sgni * rv.z * inv64 + csv + tci;
            float vw = xv[r].w + sgni * rv.w * inv64 - csv - tci;
            float4 o;
            o.x = k0 + k1 * xv[r].x + k2q * (vx * vx + a0.x + ht.x);
            o.y = k0 + k1 * xv[r].y + k2q * (vy * vy + a0.y + ht.y);
            o.z = k0 + k1 * xv[r].z + k2q * (vz * vz + a1.x + ht.z);
            o.w = k0 + k1 * xv[r].w + k2q * (vw * vw + a1.y + ht.w);
            *(float4*)&outp[i * 64 + c0] = o;
        }
    }
}

extern "C" void kernel_launch(void* const* d_in, const int* in_sizes, int n_in,
                              void* d_out, int out_size) {
    const float* x    = (const float*)d_in[0];
    const float* coef = (const float*)d_in[1];
    float* out = (float*)d_out;

    // 3 image buffers + QT(132x16B) + TR(1088x8B) + Sg(144) + Pr/Pc(2x1088) + scratch
    int smem_bytes = 3 * NB * (int)sizeof(float)
                   + 132 * 16 + 1088 * 8
                   + (144 + 2 * 1088 + 4 * 64 + 4) * (int)sizeof(float);  // ~73.3 KB
    cudaFuncSetAttribute(uppolyact_kernel,
                         cudaFuncAttributeMaxDynamicSharedMemorySize, smem_bytes);

    int nimg = in_sizes[0] / 4096;   // 4096 images of 64x64
    uppolyact_kernel<<<nimg, 256, smem_bytes>>>(x, coef, out);
}

// round 6
// speedup vs baseline: 1.6088x; 1.0053x over previous
#include <cuda_runtime.h>
#include <cmath>

#define PITCH 68
#define NB (64 * PITCH)   // 4352 floats per padded 64x64 buffer

typedef unsigned long long ull;

// Tap table passed by value (constant bank): TU[m*16+c] as float4 (g0,g1,g1,g2)
// = ulonglong2 { pair(4c+2m-64), pair(4c+2m-63) }, pair(s) = {g(s), g(s+1)}.
struct TapTable { float4 e[34 * 16]; };

__device__ __forceinline__ ull f2x2(float lo, float hi) {
    ull r; asm("mov.b64 %0, {%1, %2};" : "=l"(r) : "f"(lo), "f"(hi)); return r;
}
__device__ __forceinline__ float2 unpk(ull v) {
    float2 r; asm("mov.b64 {%0, %1}, %2;" : "=f"(r.x), "=f"(r.y) : "l"(v)); return r;
}
__device__ __forceinline__ void ffma2(ull& d, ull a, ull b) {
    asm("fma.rn.f32x2 %0, %1, %2, %0;" : "+l"(d) : "l"(a), "l"(b));
}

// Load the 10 consecutive tap pairs t[w] (TR-row u0+w, u0 = 57-SH-kb) from TU.
// SH=0: u0 odd -> 6 loads; SH=1: u0 even -> 5 loads. Compile-time .x/.y select.
template<int SH>
__device__ __forceinline__ void load_taps(ull t[10], const ulonglong2* __restrict__ TU,
                                          int kb, int lane_idx) {
    const int m0 = 28 - (kb >> 1);
    const ulonglong2* tp = TU + m0 * 16 + lane_idx;
    ulonglong2 e[6];
    #pragma unroll
    for (int j = 0; j < (SH ? 5 : 6); j++) e[j] = tp[j * 16];
    #pragma unroll
    for (int w = 0; w < 10; w++) {
        if (SH) t[w] = (w & 1) ? e[w >> 1].y : e[w >> 1].x;
        else    t[w] = (w & 1) ? e[(w + 1) >> 1].x : e[w >> 1].y;
    }
}

// Right circulant^T: dst[i][m] = sum_k src[i][k] * g(m-k-SH).
// acc[i][p] = packed {dst[r0+i][c0+2p], dst[r0+i][c0+2p+1]}.
template<int SH>
__device__ __forceinline__ void mm_right_core(ull acc[4][2], const float* __restrict__ src,
                                              const ulonglong2* __restrict__ TU,
                                              int r0, int cg) {
    #pragma unroll
    for (int r = 0; r < 4; r++) { acc[r][0] = 0ull; acc[r][1] = 0ull; }
    #pragma unroll 1
    for (int kb = 0; kb < 64; kb += 8) {
        ull t[10];
        load_taps<SH>(t, TU, kb, cg);
        #pragma unroll
        for (int i = 0; i < 4; i++) {
            float4 va = *(const float4*)&src[(r0 + i) * PITCH + kb];
            float4 vb = *(const float4*)&src[(r0 + i) * PITCH + kb + 4];
            float sv[8] = {va.x, va.y, va.z, va.w, vb.x, vb.y, vb.z, vb.w};
            #pragma unroll
            for (int q = 0; q < 8; q++) {
                ull sd = f2x2(sv[q], sv[q]);
                ffma2(acc[i][0], sd, t[7 - q]);   // pair(c0   - (kb+q) - SH)
                ffma2(acc[i][1], sd, t[9 - q]);   // pair(c0+2 - (kb+q) - SH)
            }
        }
    }
}

// Left circulant: dst[i][j] = sum_k g(i-k-SH) * src[k][j], row-pair packing:
// acc[rp][c] = packed {dst[r0+2rp][c0+c], dst[r0+2rp+1][c0+c]}.
template<int SH>
__device__ __forceinline__ void mm_leftT_core(ull acc[2][4], const float* __restrict__ src,
                                              const ulonglong2* __restrict__ TU,
                                              int rg, int c0) {
    #pragma unroll
    for (int rp = 0; rp < 2; rp++)
        #pragma unroll
        for (int c = 0; c < 4; c++) acc[rp][c] = 0ull;
    #pragma unroll 1
    for (int kb = 0; kb < 64; kb += 8) {
        ull t[10];
        load_taps<SH>(t, TU, kb, rg);
        #pragma unroll
        for (int q = 0; q < 8; q++) {
            float4 sv = *(const float4*)&src[(kb + q) * PITCH + c0];
            float s[4] = {sv.x, sv.y, sv.z, sv.w};
            #pragma unroll
            for (int c = 0; c < 4; c++) {
                ull sd = f2x2(s[c], s[c]);
                ffma2(acc[0][c], t[7 - q], sd);   // pair(r0   - (kb+q) - SH)
                ffma2(acc[1][c], t[9 - q], sd);   // pair(r0+2 - (kb+q) - SH)
            }
        }
    }
}

__device__ __forceinline__ void store_right(float* __restrict__ dst, ull acc[4][2],
                                            int r0, int c0) {
    #pragma unroll
    for (int r = 0; r < 4; r++) {
        ulonglong2 o; o.x = acc[r][0]; o.y = acc[r][1];
        *(ulonglong2*)&dst[(r0 + r) * PITCH + c0] = o;
    }
}

__global__ void __launch_bounds__(256, 3)
uppolyact_kernel(const float* __restrict__ xg,
                 const float* __restrict__ coef,
                 float* __restrict__ outg,
                 const TapTable tab) {
    extern __shared__ float sm[];
    float* B0 = sm;            // x -> oo^2
    float* B1 = sm + NB;       // Gx -> oe^2 -> tmp
    float* B2 = sm + 2 * NB;   // xG^T -> eo^2
    ulonglong2* TU = (ulonglong2*)(sm + 3 * NB);  // 544 entries (8704 B)
    float* Pr  = (float*)(TU + 544);  // 16 x 68 partials
    float* Pc  = Pr + 1088;           // 16 x 68 partials
    float* rs  = Pc + 1088;           // 64
    float* cs  = rs + 64;             // 64
    float* rs1 = cs + 64;             // 64
    float* cs2 = rs1 + 64;            // 64
    float* tsp = cs2 + 64;            // 1

    const int tid = threadIdx.x;
    const int rg = tid >> 4, cg = tid & 15;
    const int r0 = rg << 2, c0 = cg << 2;
    const float* xin = xg + (size_t)blockIdx.x * 4096;
    float* outp = outg + (size_t)blockIdx.x * 4096;

    const float k0 = __ldg(&coef[0]), k1 = __ldg(&coef[1]);
    const float k2q = 0.25f * __ldg(&coef[2]);

    // ---- P0: copy tap table param -> smem; load image; x rank-1 partials ----
    {
        const ulonglong2* TUp = (const ulonglong2*)tab.e;
        #pragma unroll
        for (int i = tid; i < 544; i += 256) TU[i] = TUp[i];
    }
    {
        float4 xv[4];
        #pragma unroll
        for (int r = 0; r < 4; r++) {
            xv[r] = *(const float4*)&xin[(r0 + r) * 64 + c0];
            *(float4*)&B0[(r0 + r) * PITCH + c0] = xv[r];
        }
        float4 pr;   // sum_r (-1)^r x[r][j] partial (r0 even -> sign +)
        pr.x = xv[0].x - xv[1].x + xv[2].x - xv[3].x;
        pr.y = xv[0].y - xv[1].y + xv[2].y - xv[3].y;
        pr.z = xv[0].z - xv[1].z + xv[2].z - xv[3].z;
        pr.w = xv[0].w - xv[1].w + xv[2].w - xv[3].w;
        *(float4*)&Pr[rg * 68 + c0] = pr;
        float4 pc;   // sum_c (-1)^c x[i][c] partial
        pc.x = xv[0].x - xv[0].y + xv[0].z - xv[0].w;
        pc.y = xv[1].x - xv[1].y + xv[1].z - xv[1].w;
        pc.z = xv[2].x - xv[2].y + xv[2].z - xv[2].w;
        pc.w = xv[3].x - xv[3].y + xv[3].z - xv[3].w;
        *(float4*)&Pc[cg * 68 + r0] = pc;
    }
    __syncthreads();

    // ---- P1: rs/cs reduce (tid<64, overlapped) + B1 = Gx ; B2 = xG^T ----
    if (tid < 64) {
        float s = 0.f, t = 0.f;
        #pragma unroll
        for (int g = 0; g < 16; g++) { s += Pr[g * 68 + tid]; t += Pc[g * 68 + tid]; }
        rs[tid] = s; cs[tid] = t;
    }
    {
        ull a1[2][4], a2[4][2];
        mm_leftT_core<0>(a1, B0, TU, rg, c0);
        mm_right_core<0>(a2, B0, TU, r0, cg);
        // rs1 partials: alt row-sums of xG^T (a2, col-pair layout)
        {
            float2 u0 = unpk(a2[0][0]), u1 = unpk(a2[1][0]),
                   u2 = unpk(a2[2][0]), u3 = unpk(a2[3][0]);
            float2 w0 = unpk(a2[0][1]), w1 = unpk(a2[1][1]),
                   w2 = unpk(a2[2][1]), w3 = unpk(a2[3][1]);
            float4 p;
            p.x = u0.x - u1.x + u2.x - u3.x;
            p.y = u0.y - u1.y + u2.y - u3.y;
            p.z = w0.x - w1.x + w2.x - w3.x;
            p.w = w0.y - w1.y + w2.y - w3.y;
            *(float4*)&Pr[rg * 68 + c0] = p;
        }
        // cs2 partials: alt col-sums of Gx (a1, row-pair layout)
        {
            float2 v0 = unpk(a1[0][0]), v1 = unpk(a1[0][1]),
                   v2 = unpk(a1[0][2]), v3 = unpk(a1[0][3]);
            float2 y0 = unpk(a1[1][0]), y1 = unpk(a1[1][1]),
                   y2 = unpk(a1[1][2]), y3 = unpk(a1[1][3]);
            float4 p;
            p.x = v0.x - v1.x + v2.x - v3.x;   // row r0
            p.y = v0.y - v1.y + v2.y - v3.y;   // row r0+1
            p.z = y0.x - y1.x + y2.x - y3.x;   // row r0+2
            p.w = y0.y - y1.y + y2.y - y3.y;   // row r0+3
            *(float4*)&Pc[cg * 68 + r0] = p;
            // store Gx -> B1 (row-pair unpack)
            #pragma unroll
            for (int rp = 0; rp < 2; rp++) {
                float2 a = unpk(a1[rp][0]), b = unpk(a1[rp][1]),
                       c = unpk(a1[rp][2]), d = unpk(a1[rp][3]);
                *(float4*)&B1[(r0 + 2 * rp) * PITCH + c0] =
                    make_float4(a.x, b.x, c.x, d.x);
                *(float4*)&B1[(r0 + 2 * rp + 1) * PITCH + c0] =
                    make_float4(a.y, b.y, c.y, d.y);
            }
        }
        store_right(B2, a2, r0, c0);
    }
    __syncthreads();

    // ---- P2a: rs1/cs2/ts reduces (overlapped) + oo = (Gx)G^T compute ----
    if (tid < 64) {
        float s = 0.f, t = 0.f;
        #pragma unroll
        for (int g = 0; g < 16; g++) { s += Pr[g * 68 + tid]; t += Pc[g * 68 + tid]; }
        rs1[tid] = s; cs2[tid] = t;
    } else if (tid < 96) {
        int l = tid - 64;
        float v = rs[2 * l] - rs[2 * l + 1];
        #pragma unroll
        for (int o = 16; o > 0; o >>= 1)
            v += __shfl_xor_sync(0xffffffffu, v, o);
        if (l == 0) tsp[0] = v;
    }
    ull a3[4][2];
    mm_right_core<0>(a3, B1, TU, r0, cg);
    __syncthreads();

    // ---- P2b: apply rank-1 corrections, square phases: B0<-oo^2 B1<-oe^2 B2<-eo^2 ----
    {
        const float inv64 = 1.0f / 64.0f;
        float4 rv1 = *(const float4*)&rs1[c0];
        #pragma unroll
        for (int r = 0; r < 4; r++) {
            int i = r0 + r;
            float sgni = (i & 1) ? -1.f : 1.f;
            float cs2v = cs2[i] * inv64;
            int base = i * PITCH + c0;
            float4 v1 = *(float4*)&B1[base];   // Gx   -> oe
            float4 v2 = *(float4*)&B2[base];   // xG^T -> eo
            float2 o0 = unpk(a3[r][0]), o1 = unpk(a3[r][1]);
            float4 eo, oe, oo;
            eo.x = v2.x + sgni * rv1.x * inv64;
            eo.y = v2.y + sgni * rv1.y * inv64;
            eo.z = v2.z + sgni * rv1.z * inv64;
            eo.w = v2.w + sgni * rv1.w * inv64;
            oe.x = v1.x + cs2v;  oe.y = v1.y - cs2v;
            oe.z = v1.z + cs2v;  oe.w = v1.w - cs2v;
            oo.x = o0.x; oo.y = o0.y; oo.z = o1.x; oo.w = o1.y;
            eo.x *= eo.x; eo.y *= eo.y; eo.z *= eo.z; eo.w *= eo.w;
            oe.x *= oe.x; oe.y *= oe.y; oe.z *= oe.z; oe.w *= oe.w;
            oo.x *= oo.x; oo.y *= oo.y; oo.z *= oo.z; oo.w *= oo.w;
            *(float4*)&B2[base] = eo;
            *(float4*)&B1[base] = oe;
            *(float4*)&B0[base] = oo;
        }
    }
    __syncthreads();

    // ---- P3: tmp: B1 = oe^2 + oo^2 G'^T  (G' = g shifted; in-place own tile) ----
    {
        ull acc[4][2];
        mm_right_core<1>(acc, B0, TU, r0, cg);
        #pragma unroll
        for (int r = 0; r < 4; r++) {
            int base = (r0 + r) * PITCH + c0;
            float4 d = *(float4*)&B1[base];
            float2 a0 = unpk(acc[r][0]), a1 = unpk(acc[r][1]);
            d.x += a0.x;  d.y += a0.y;  d.z += a1.x;  d.w += a1.y;
            *(float4*)&B1[base] = d;
        }
    }
    __syncthreads();

    // ---- P4+P5 fused: F = G'*tmp (regs), E = eo^2 G'^T (regs), final combine ----
    {
        ull Fa[2][4], Ea[4][2];
        mm_leftT_core<1>(Fa, B1, TU, rg, c0);
        mm_right_core<1>(Ea, B2, TU, r0, cg);
        // Unpack F into per-row layout
        float Ff[4][4];
        #pragma unroll
        for (int rp = 0; rp < 2; rp++)
            #pragma unroll
            for (int c = 0; c < 4; c++) {
                float2 u = unpk(Fa[rp][c]);
                Ff[2 * rp][c] = u.x;
                Ff[2 * rp + 1][c] = u.y;
            }
        const float ts = tsp[0];
        const float inv64 = 1.0f / 64.0f;
        const float inv4096 = inv64 * inv64;
        float4 rv = *(const float4*)&rs[c0];
        #pragma unroll
        for (int r = 0; r < 4; r++) {
            int i = r0 + r;
            float sgni = (i & 1) ? -1.f : 1.f;
            float4 xv = *(const float4*)&xin[i * 64 + c0];
            float2 a0 = unpk(Ea[r][0]), a1 = unpk(Ea[r][1]);
            float csv = cs[i] * inv64;
            float tci = sgni * ts * inv4096;
            float vx = xv.x + sgni * rv.x * inv64 + csv + tci;
            float vy = xv.y + sgni * rv.y * inv64 - csv - tci;
            float vz = xv.z + sgni * rv.z * inv64 + csv + tci;
            float vw = xv.w + sgni * rv.w * inv64 - csv - tci;
            float4 o;
            o.x = k0 + k1 * xv.x + k2q * (vx * vx + a0.x + Ff[r][0]);
            o.y = k0 + k1 * xv.y + k2q * (vy * vy + a0.y + Ff[r][1]);
            o.z = k0 + k1 * xv.z + k2q * (vz * vz + a1.x + Ff[r][2]);
            o.w = k0 + k1 * xv.w + k2q * (vw * vw + a1.y + Ff[r][3]);
            *(float4*)&outp[i * 64 + c0] = o;
        }
    }
}

// Host-side tap computation (double precision, exact integer angle reduction).
static double host_g(int t) {
    const double PI_D = 3.14159265358979323846;
    long long m = 2LL * t + 1;
    int r1 = (int)(((63LL * m) % 256 + 256) % 256); if (r1 >= 128) r1 -= 256;
    int r2 = (int)((m % 256 + 256) % 256);          if (r2 >= 128) r2 -= 256;
    return (sin(PI_D * r1 / 128.0) / sin(PI_D * r2 / 128.0)) / 64.0;
}

extern "C" void kernel_launch(void* const* d_in, const int* in_sizes, int n_in,
                              void* d_out, int out_size) {
    const float* x    = (const float*)d_in[0];
    const float* coef = (const float*)d_in[1];
    float* out = (float*)d_out;

    static TapTable tab;
    static bool tab_init = false;
    if (!tab_init) {
        for (int m = 0; m < 34; m++)
            for (int c = 0; c < 16; c++) {
                int s = 4 * c + 2 * m - 64;
                float g0 = (float)host_g(s);
                float g1 = (float)host_g(s + 1);
                float g2 = (float)host_g(s + 2);
                tab.e[m * 16 + c] = make_float4(g0, g1, g1, g2);
            }
        tab_init = true;
    }

    // 3 buffers + TU(544x16B) + Pr/Pc + scratch
    int smem_bytes = 3 * NB * (int)sizeof(float)
                   + 544 * 16
                   + (2 * 1088 + 4 * 64 + 4) * (int)sizeof(float);   // ~70.7 KB
    cudaFuncSetAttribute(uppolyact_kernel,
                         cudaFuncAttributeMaxDynamicSharedMemorySize, smem_bytes);

    int nimg = in_sizes[0] / 4096;   // 4096 images of 64x64
    uppolyact_kernel<<<nimg, 256, smem_bytes>>>(x, coef, out, tab);
}

// round 7
// speedup vs baseline: 1.6094x; 1.0004x over previous
#include <cuda_runtime.h>
#include <cmath>

#define PITCH 68
#define NB (64 * PITCH)   // 4352 floats per padded 64x64 buffer

typedef unsigned long long ull;

// Tap table passed by value (constant bank): TU[m*16+c] as float4 (g0,g1,g1,g2)
// = ulonglong2 { pair(4c+2m-64), pair(4c+2m-63) }, pair(s) = {g(s), g(s+1)}.
struct TapTable { float4 e[34 * 16]; };

__device__ __forceinline__ ull f2x2(float lo, float hi) {
    ull r; asm("mov.b64 %0, {%1, %2};" : "=l"(r) : "f"(lo), "f"(hi)); return r;
}
__device__ __forceinline__ float2 unpk(ull v) {
    float2 r; asm("mov.b64 {%0, %1}, %2;" : "=f"(r.x), "=f"(r.y) : "l"(v)); return r;
}
__device__ __forceinline__ void ffma2(ull& d, ull a, ull b) {
    asm("fma.rn.f32x2 %0, %1, %2, %0;" : "+l"(d) : "l"(a), "l"(b));
}

// Load the 10 consecutive tap pairs t[w] (TR-row u0+w, u0 = 57-SH-kb) from TU.
// SH=0: u0 odd -> 6 loads; SH=1: u0 even -> 5 loads. Compile-time .x/.y select.
template<int SH>
__device__ __forceinline__ void load_taps(ull t[10], const ulonglong2* __restrict__ TU,
                                          int kb, int lane_idx) {
    const int m0 = 28 - (kb >> 1);
    const ulonglong2* tp = TU + m0 * 16 + lane_idx;
    ulonglong2 e[6];
    #pragma unroll
    for (int j = 0; j < (SH ? 5 : 6); j++) e[j] = tp[j * 16];
    #pragma unroll
    for (int w = 0; w < 10; w++) {
        if (SH) t[w] = (w & 1) ? e[w >> 1].y : e[w >> 1].x;
        else    t[w] = (w & 1) ? e[(w + 1) >> 1].x : e[w >> 1].y;
    }
}

// Right circulant^T: dst[i][m] = sum_k src[i][k] * g(m-k-SH).
// acc[i][p] = packed {dst[r0+i][c0+2p], dst[r0+i][c0+2p+1]}.
template<int SH>
__device__ __forceinline__ void mm_right_core(ull acc[4][2], const float* __restrict__ src,
                                              const ulonglong2* __restrict__ TU,
                                              int r0, int cg) {
    #pragma unroll
    for (int r = 0; r < 4; r++) { acc[r][0] = 0ull; acc[r][1] = 0ull; }
    #pragma unroll 1
    for (int kb = 0; kb < 64; kb += 8) {
        ull t[10];
        load_taps<SH>(t, TU, kb, cg);
        #pragma unroll
        for (int i = 0; i < 4; i++) {
            float4 va = *(const float4*)&src[(r0 + i) * PITCH + kb];
            float4 vb = *(const float4*)&src[(r0 + i) * PITCH + kb + 4];
            float sv[8] = {va.x, va.y, va.z, va.w, vb.x, vb.y, vb.z, vb.w};
            #pragma unroll
            for (int q = 0; q < 8; q++) {
                ull sd = f2x2(sv[q], sv[q]);
                ffma2(acc[i][0], sd, t[7 - q]);   // pair(c0   - (kb+q) - SH)
                ffma2(acc[i][1], sd, t[9 - q]);   // pair(c0+2 - (kb+q) - SH)
            }
        }
    }
}

// Left circulant: dst[i][j] = sum_k g(i-k-SH) * src[k][j], row-pair packing:
// acc[rp][c] = packed {dst[r0+2rp][c0+c], dst[r0+2rp+1][c0+c]}.
template<int SH>
__device__ __forceinline__ void mm_leftT_core(ull acc[2][4], const float* __restrict__ src,
                                              const ulonglong2* __restrict__ TU,
                                              int rg, int c0) {
    #pragma unroll
    for (int rp = 0; rp < 2; rp++)
        #pragma unroll
        for (int c = 0; c < 4; c++) acc[rp][c] = 0ull;
    #pragma unroll 1
    for (int kb = 0; kb < 64; kb += 8) {
        ull t[10];
        load_taps<SH>(t, TU, kb, rg);
        #pragma unroll
        for (int q = 0; q < 8; q++) {
            float4 sv = *(const float4*)&src[(kb + q) * PITCH + c0];
            float s[4] = {sv.x, sv.y, sv.z, sv.w};
            #pragma unroll
            for (int c = 0; c < 4; c++) {
                ull sd = f2x2(s[c], s[c]);
                ffma2(acc[0][c], t[7 - q], sd);   // pair(r0   - (kb+q) - SH)
                ffma2(acc[1][c], t[9 - q], sd);   // pair(r0+2 - (kb+q) - SH)
            }
        }
    }
}

__device__ __forceinline__ void store_right(float* __restrict__ dst, ull acc[4][2],
                                            int r0, int c0) {
    #pragma unroll
    for (int r = 0; r < 4; r++) {
        ulonglong2 o; o.x = acc[r][0]; o.y = acc[r][1];
        *(ulonglong2*)&dst[(r0 + r) * PITCH + c0] = o;
    }
}

__global__ void __launch_bounds__(256, 3)
uppolyact_kernel(const float* __restrict__ xg,
                 const float* __restrict__ coef,
                 float* __restrict__ outg,
                 const TapTable tab) {
    extern __shared__ float sm[];
    float* B0 = sm;            // x -> oo^2
    float* B1 = sm + NB;       // Gx -> oe^2 -> tmp
    float* B2 = sm + 2 * NB;   // xG^T -> eo^2
    ulonglong2* TU = (ulonglong2*)(sm + 3 * NB);  // 544 entries (8704 B)
    float* Pr  = (float*)(TU + 544);  // 16 x 68 partials
    float* Pc  = Pr + 1088;           // 16 x 68 partials
    float* rs  = Pc + 1088;           // 64
    float* cs  = rs + 64;             // 64
    float* rs1 = cs + 64;             // 64
    float* cs2 = rs1 + 64;            // 64
    float* tsp = cs2 + 64;            // 1

    const int tid = threadIdx.x;
    const int rg = tid >> 4, cg = tid & 15;
    const int r0 = rg << 2, c0 = cg << 2;
    const float* xin = xg + (size_t)blockIdx.x * 4096;
    float* outp = outg + (size_t)blockIdx.x * 4096;

    const float k0 = __ldg(&coef[0]), k1 = __ldg(&coef[1]);
    const float k2q = 0.25f * __ldg(&coef[2]);

    // ---- P0: copy tap table param -> smem; load image; x rank-1 partials ----
    {
        const ulonglong2* TUp = (const ulonglong2*)tab.e;
        #pragma unroll
        for (int i = tid; i < 544; i += 256) TU[i] = TUp[i];
    }
    {
        float4 xv[4];
        #pragma unroll
        for (int r = 0; r < 4; r++) {
            xv[r] = *(const float4*)&xin[(r0 + r) * 64 + c0];
            *(float4*)&B0[(r0 + r) * PITCH + c0] = xv[r];
        }
        float4 pr;   // sum_r (-1)^r x[r][j] partial (r0 even -> sign +)
        pr.x = xv[0].x - xv[1].x + xv[2].x - xv[3].x;
        pr.y = xv[0].y - xv[1].y + xv[2].y - xv[3].y;
        pr.z = xv[0].z - xv[1].z + xv[2].z - xv[3].z;
        pr.w = xv[0].w - xv[1].w + xv[2].w - xv[3].w;
        *(float4*)&Pr[rg * 68 + c0] = pr;
        float4 pc;   // sum_c (-1)^c x[i][c] partial
        pc.x = xv[0].x - xv[0].y + xv[0].z - xv[0].w;
        pc.y = xv[1].x - xv[1].y + xv[1].z - xv[1].w;
        pc.z = xv[2].x - xv[2].y + xv[2].z - xv[2].w;
        pc.w = xv[3].x - xv[3].y + xv[3].z - xv[3].w;
        *(float4*)&Pc[cg * 68 + r0] = pc;
    }
    __syncthreads();

    // ---- P1: rs/cs reduce (tid<64, overlapped) + B1 = Gx ; B2 = xG^T ----
    if (tid < 64) {
        float s = 0.f, t = 0.f;
        #pragma unroll
        for (int g = 0; g < 16; g++) { s += Pr[g * 68 + tid]; t += Pc[g * 68 + tid]; }
        rs[tid] = s; cs[tid] = t;
    }
    {
        ull a1[2][4], a2[4][2];
        mm_leftT_core<0>(a1, B0, TU, rg, c0);
        mm_right_core<0>(a2, B0, TU, r0, cg);
        // rs1 partials: alt row-sums of xG^T (a2, col-pair layout)
        {
            float2 u0 = unpk(a2[0][0]), u1 = unpk(a2[1][0]),
                   u2 = unpk(a2[2][0]), u3 = unpk(a2[3][0]);
            float2 w0 = unpk(a2[0][1]), w1 = unpk(a2[1][1]),
                   w2 = unpk(a2[2][1]), w3 = unpk(a2[3][1]);
            float4 p;
            p.x = u0.x - u1.x + u2.x - u3.x;
            p.y = u0.y - u1.y + u2.y - u3.y;
            p.z = w0.x - w1.x + w2.x - w3.x;
            p.w = w0.y - w1.y + w2.y - w3.y;
            *(float4*)&Pr[rg * 68 + c0] = p;
        }
        // cs2 partials: alt col-sums of Gx (a1, row-pair layout)
        {
            float2 v0 = unpk(a1[0][0]), v1 = unpk(a1[0][1]),
                   v2 = unpk(a1[0][2]), v3 = unpk(a1[0][3]);
            float2 y0 = unpk(a1[1][0]), y1 = unpk(a1[1][1]),
                   y2 = unpk(a1[1][2]), y3 = unpk(a1[1][3]);
            float4 p;
            p.x = v0.x - v1.x + v2.x - v3.x;   // row r0
            p.y = v0.y - v1.y + v2.y - v3.y;   // row r0+1
            p.z = y0.x - y1.x + y2.x - y3.x;   // row r0+2
            p.w = y0.y - y1.y + y2.y - y3.y;   // row r0+3
            *(float4*)&Pc[cg * 68 + r0] = p;
            // store Gx -> B1 (row-pair unpack)
            #pragma unroll
            for (int rp = 0; rp < 2; rp++) {
                float2 a = unpk(a1[rp][0]), b = unpk(a1[rp][1]),
                       c = unpk(a1[rp][2]), d = unpk(a1[rp][3]);
                *(float4*)&B1[(r0 + 2 * rp) * PITCH + c0] =
                    make_float4(a.x, b.x, c.x, d.x);
                *(float4*)&B1[(r0 + 2 * rp + 1) * PITCH + c0] =
                    make_float4(a.y, b.y, c.y, d.y);
            }
        }
        store_right(B2, a2, r0, c0);
    }
    __syncthreads();

    // ---- P2a: rs1/cs2/ts reduces (overlapped) + oo = (Gx)G^T compute ----
    if (tid < 64) {
        float s = 0.f, t = 0.f;
        #pragma unroll
        for (int g = 0; g < 16; g++) { s += Pr[g * 68 + tid]; t += Pc[g * 68 + tid]; }
        rs1[tid] = s; cs2[tid] = t;
    } else if (tid < 96) {
        int l = tid - 64;
        float v = rs[2 * l] - rs[2 * l + 1];
        #pragma unroll
        for (int o = 16; o > 0; o >>= 1)
            v += __shfl_xor_sync(0xffffffffu, v, o);
        if (l == 0) tsp[0] = v;
    }
    ull a3[4][2];
    mm_right_core<0>(a3, B1, TU, r0, cg);
    __syncthreads();

    // ---- P2b: apply rank-1 corrections, square phases: B0<-oo^2 B1<-oe^2 B2<-eo^2 ----
    {
        const float inv64 = 1.0f / 64.0f;
        float4 rv1 = *(const float4*)&rs1[c0];
        #pragma unroll
        for (int r = 0; r < 4; r++) {
            int i = r0 + r;
            float sgni = (i & 1) ? -1.f : 1.f;
            float cs2v = cs2[i] * inv64;
            int base = i * PITCH + c0;
            float4 v1 = *(float4*)&B1[base];   // Gx   -> oe
            float4 v2 = *(float4*)&B2[base];   // xG^T -> eo
            float2 o0 = unpk(a3[r][0]), o1 = unpk(a3[r][1]);
            float4 eo, oe, oo;
            eo.x = v2.x + sgni * rv1.x * inv64;
            eo.y = v2.y + sgni * rv1.y * inv64;
            eo.z = v2.z + sgni * rv1.z * inv64;
            eo.w = v2.w + sgni * rv1.w * inv64;
            oe.x = v1.x + cs2v;  oe.y = v1.y - cs2v;
            oe.z = v1.z + cs2v;  oe.w = v1.w - cs2v;
            oo.x = o0.x; oo.y = o0.y; oo.z = o1.x; oo.w = o1.y;
            eo.x *= eo.x; eo.y *= eo.y; eo.z *= eo.z; eo.w *= eo.w;
            oe.x *= oe.x; oe.y *= oe.y; oe.z *= oe.z; oe.w *= oe.w;
            oo.x *= oo.x; oo.y *= oo.y; oo.z *= oo.z; oo.w *= oo.w;
            *(float4*)&B2[base] = eo;
            *(float4*)&B1[base] = oe;
            *(float4*)&B0[base] = oo;
        }
    }
    __syncthreads();

    // ---- P3: tmp: B1 = oe^2 + oo^2 G'^T  (G' = g shifted; in-place own tile) ----
    {
        ull acc[4][2];
        mm_right_core<1>(acc, B0, TU, r0, cg);
        #pragma unroll
        for (int r = 0; r < 4; r++) {
            int base = (r0 + r) * PITCH + c0;
            float4 d = *(float4*)&B1[base];
            float2 a0 = unpk(acc[r][0]), a1 = unpk(acc[r][1]);
            d.x += a0.x;  d.y += a0.y;  d.z += a1.x;  d.w += a1.y;
            *(float4*)&B1[base] = d;
        }
    }
    __syncthreads();

    // ---- P4+P5 fused: F = G'*tmp (regs), E = eo^2 G'^T (regs), final combine ----
    {
        ull Fa[2][4], Ea[4][2];
        mm_leftT_core<1>(Fa, B1, TU, rg, c0);
        mm_right_core<1>(Ea, B2, TU, r0, cg);
        // Unpack F into per-row layout
        float Ff[4][4];
        #pragma unroll
        for (int rp = 0; rp < 2; rp++)
            #pragma unroll
            for (int c = 0; c < 4; c++) {
                float2 u = unpk(Fa[rp][c]);
                Ff[2 * rp][c] = u.x;
                Ff[2 * rp + 1][c] = u.y;
            }
        const float ts = tsp[0];
        const float inv64 = 1.0f / 64.0f;
        const float inv4096 = inv64 * inv64;
        float4 rv = *(const float4*)&rs[c0];
        #pragma unroll
        for (int r = 0; r < 4; r++) {
            int i = r0 + r;
            float sgni = (i & 1) ? -1.f : 1.f;
            float4 xv = *(const float4*)&xin[i * 64 + c0];
            float2 a0 = unpk(Ea[r][0]), a1 = unpk(Ea[r][1]);
            float csv = cs[i] * inv64;
            float tci = sgni * ts * inv4096;
            float vx = xv.x + sgni * rv.x * inv64 + csv + tci;
            float vy = xv.y + sgni * rv.y * inv64 - csv - tci;
            float vz = xv.z + sgni * rv.z * inv64 + csv + tci;
            float vw = xv.w + sgni * rv.w * inv64 - csv - tci;
            float4 o;
            o.x = k0 + k1 * xv.x + k2q * (vx * vx + a0.x + Ff[r][0]);
            o.y = k0 + k1 * xv.y + k2q * (vy * vy + a0.y + Ff[r][1]);
            o.z = k0 + k1 * xv.z + k2q * (vz * vz + a1.x + Ff[r][2]);
            o.w = k0 + k1 * xv.w + k2q * (vw * vw + a1.y + Ff[r][3]);
            *(float4*)&outp[i * 64 + c0] = o;
        }
    }
}

// Host-side tap computation (double precision, exact integer angle reduction).
static double host_g(int t) {
    const double PI_D = 3.14159265358979323846;
    long long m = 2LL * t + 1;
    int r1 = (int)(((63LL * m) % 256 + 256) % 256); if (r1 >= 128) r1 -= 256;
    int r2 = (int)((m % 256 + 256) % 256);          if (r2 >= 128) r2 -= 256;
    return (sin(PI_D * r1 / 128.0) / sin(PI_D * r2 / 128.0)) / 64.0;
}

extern "C" void kernel_launch(void* const* d_in, const int* in_sizes, int n_in,
                              void* d_out, int out_size) {
    const float* x    = (const float*)d_in[0];
    const float* coef = (const float*)d_in[1];
    float* out = (float*)d_out;

    static TapTable tab;
    static bool tab_init = false;
    if (!tab_init) {
        for (int m = 0; m < 34; m++)
            for (int c = 0; c < 16; c++) {
                int s = 4 * c + 2 * m - 64;
                float g0 = (float)host_g(s);
                float g1 = (float)host_g(s + 1);
                float g2 = (float)host_g(s + 2);
                tab.e[m * 16 + c] = make_float4(g0, g1, g1, g2);
            }
        tab_init = true;
    }

    // 3 buffers + TU(544x16B) + Pr/Pc + scratch
    int smem_bytes = 3 * NB * (int)sizeof(float)
                   + 544 * 16
                   + (2 * 1088 + 4 * 64 + 4) * (int)sizeof(float);   // ~70.7 KB
    cudaFuncSetAttribute(uppolyact_kernel,
                         cudaFuncAttributeMaxDynamicSharedMemorySize, smem_bytes);

    int nimg = in_sizes[0] / 4096;   // 4096 images of 64x64
    uppolyact_kernel<<<nimg, 256, smem_bytes>>>(x, coef, out, tab);
}